// round 2
// baseline (speedup 1.0000x reference)
#include <cuda_runtime.h>
#include <cuda_fp16.h>
#include <cstdint>

// ============================================================================
// BinLinear: C[8192,2048] = A[8192,2048] @ sign(W[2048,2048])
// compute_100 PTX target => NO tcgen05. Use Ampere-style mma.sync (HMMA).
// Plan:
//   prep1: A fp32 -> fp16 (rel err 2^-11; fp32 accum in MMA => norm rel ~3e-4)
//   prep2: W fp32 -> Wb[n][k] = sign(W[k][n]) in fp16 (+-1 exact), K-major
//   gemm:  128x128x2048 per CTA, BK=64, SW128-swizzled smem, cp.async 3-stage,
//          4 warps, warp tile 64x64, m16n8k16 f16 MMA, fp32 accumulators.
// ============================================================================

#define DEV_INLINE __device__ __forceinline__

static constexpr int MDIM = 8192;
static constexpr int KDIM = 2048;
static constexpr int NDIM = 2048;

static constexpr int BM = 128;
static constexpr int BN = 128;
static constexpr int BK = 64;                    // 64 fp16 = 128 B = SW128 row
static constexpr int NCHUNK = KDIM / BK;         // 32
static constexpr int NSTAGE = 3;

static constexpr uint32_t STAGE_A = 0;
static constexpr uint32_t STAGE_B = 128 * 128;   // 16384 B (A tile bytes)
static constexpr uint32_t STAGE_BYTES = 32768;   // A + B
static constexpr int SMEM_TOTAL = NSTAGE * (int)STAGE_BYTES;  // 98304

// Scratch (allocation-free: __device__ globals)
__device__ __half g_A16[(size_t)MDIM * KDIM];
__device__ __half g_Wb[(size_t)NDIM * KDIM];     // [n][k] = sign(W[k][n])

// ---------------------------------------------------------------------------
// helpers
// ---------------------------------------------------------------------------
DEV_INLINE uint32_t smem_u32(const void* p) {
    uint32_t a;
    asm("{ .reg .u64 t; cvta.to.shared.u64 t, %1; cvt.u32.u64 %0, t; }"
        : "=r"(a) : "l"(p));
    return a;
}

DEV_INLINE void cp_async16(uint32_t dst, const void* src) {
    asm volatile("cp.async.cg.shared.global [%0], [%1], 16;"
                 :: "r"(dst), "l"(src));
}
DEV_INLINE void cp_commit() { asm volatile("cp.async.commit_group;" ::: "memory"); }
template <int NMAX>
DEV_INLINE void cp_wait() { asm volatile("cp.async.wait_group %0;" :: "n"(NMAX) : "memory"); }

DEV_INLINE uint32_t sw128(uint32_t off) { return off ^ ((off >> 3) & 0x70); }

DEV_INLINE void ldsm_x4(uint32_t& r0, uint32_t& r1, uint32_t& r2, uint32_t& r3,
                        uint32_t addr) {
    asm volatile("ldmatrix.sync.aligned.m8n8.x4.shared.b16 {%0,%1,%2,%3}, [%4];"
                 : "=r"(r0), "=r"(r1), "=r"(r2), "=r"(r3) : "r"(addr));
}

DEV_INLINE void mma16816(float* c, const uint32_t* a, uint32_t b0, uint32_t b1) {
    asm volatile(
        "mma.sync.aligned.m16n8k16.row.col.f32.f16.f16.f32 "
        "{%0,%1,%2,%3}, {%4,%5,%6,%7}, {%8,%9}, {%0,%1,%2,%3};"
        : "+f"(c[0]), "+f"(c[1]), "+f"(c[2]), "+f"(c[3])
        : "r"(a[0]), "r"(a[1]), "r"(a[2]), "r"(a[3]), "r"(b0), "r"(b1));
}

// ---------------------------------------------------------------------------
// Prep 1: A fp32 -> fp16
// ---------------------------------------------------------------------------
__global__ void convert_kernel(const float* __restrict__ A) {
    size_t i = ((size_t)blockIdx.x * blockDim.x + threadIdx.x) * 4;
    float4 a = *reinterpret_cast<const float4*>(A + i);
    __half2 h0 = __floats2half2_rn(a.x, a.y);
    __half2 h1 = __floats2half2_rn(a.z, a.w);
    *reinterpret_cast<__half2*>(g_A16 + i)     = h0;
    *reinterpret_cast<__half2*>(g_A16 + i + 2) = h1;
}

// ---------------------------------------------------------------------------
// Prep 2: binarize + transpose W -> Wb[n][k] = sign(W[k][n]) in fp16.
// sign(tanh(w)) == (w >= 0 ? +1 : -1); -0.0 >= 0 true, matches jnp.where.
// ---------------------------------------------------------------------------
__global__ void binarize_kernel(const float* __restrict__ W) {
    __shared__ float tile[32][33];
    int j0 = blockIdx.x * 32;   // N (num_op)
    int i0 = blockIdx.y * 32;   // K (num_ip)
    int tx = threadIdx.x, ty = threadIdx.y;
    #pragma unroll
    for (int r = ty; r < 32; r += 8)
        tile[r][tx] = W[(size_t)(i0 + r) * NDIM + j0 + tx];
    __syncthreads();
    #pragma unroll
    for (int r = ty; r < 32; r += 8) {
        float v = tile[tx][r];  // W[i0+tx][j0+r]
        g_Wb[(size_t)(j0 + r) * KDIM + i0 + tx] =
            __float2half(v >= 0.0f ? 1.0f : -1.0f);
    }
}

// ---------------------------------------------------------------------------
// GEMM: grid 1024 CTAs of 128 threads, 2 CTAs/SM.
// ---------------------------------------------------------------------------
DEV_INLINE void load_stage(uint32_t stage_base, int tid, int m0, int n0, int k0) {
    const char* Ab = reinterpret_cast<const char*>(g_A16 + (size_t)m0 * KDIM + k0);
    const char* Bb = reinterpret_cast<const char*>(g_Wb  + (size_t)n0 * KDIM + k0);
    const size_t rs = (size_t)KDIM * 2;  // 4096 B row stride
    #pragma unroll
    for (int it = 0; it < 8; ++it) {     // A: 128 rows x 8 x 16B granules
        int g = tid + it * 128;
        int row = g >> 3, seg = g & 7;
        uint32_t so = sw128((uint32_t)(row * 128 + seg * 16));
        cp_async16(stage_base + STAGE_A + so, Ab + (size_t)row * rs + seg * 16);
    }
    #pragma unroll
    for (int it = 0; it < 8; ++it) {     // B: 128 rows x 8 x 16B granules
        int g = tid + it * 128;
        int row = g >> 3, seg = g & 7;
        uint32_t so = sw128((uint32_t)(row * 128 + seg * 16));
        cp_async16(stage_base + STAGE_B + so, Bb + (size_t)row * rs + seg * 16);
    }
}

__global__ void __launch_bounds__(128, 2)
gemm_kernel(float* __restrict__ out) {
    extern __shared__ __align__(1024) char smem[];
    const uint32_t sb = smem_u32(smem);
    const int tid = threadIdx.x;
    const int lane = tid & 31;
    const int wid = tid >> 5;
    const int warp_m = wid >> 1;         // 0..1 -> m offset 64*warp_m
    const int warp_n = wid & 1;          // 0..1 -> n offset 64*warp_n

    const int ntiles = NDIM / BN;        // 16
    const int n0 = (blockIdx.x % ntiles) * BN;
    const int m0 = (blockIdx.x / ntiles) * BM;

    // ldmatrix source row/byte patterns (per-thread invariant parts)
    const int a_row = warp_m * 64 + (lane & 15);          // + mt*16
    const int a_kb  = ((lane >> 4) << 4);                  // + ks*32
    const int b_row = warp_n * 64 + (lane & 7) + ((lane >> 4) << 3);  // + ntp*16
    const int b_kb  = (((lane >> 3) & 1) << 4);            // + ks*32

    float c[4][8][4] = {};  // [mt][nt][reg]

    // Prologue: stages 0..NSTAGE-2
    #pragma unroll
    for (int p = 0; p < NSTAGE - 1; ++p) {
        load_stage(sb + p * STAGE_BYTES, tid, m0, n0, p * BK);
        cp_commit();
    }

    for (int kc = 0; kc < NCHUNK; ++kc) {
        cp_wait<NSTAGE - 2>();
        __syncthreads();

        // issue loads for chunk kc+NSTAGE-1 into the buffer freed last iter
        {
            const int nk = kc + NSTAGE - 1;
            if (nk < NCHUNK)
                load_stage(sb + (nk % NSTAGE) * STAGE_BYTES, tid, m0, n0, nk * BK);
            cp_commit();
        }

        const uint32_t abase = sb + (kc % NSTAGE) * STAGE_BYTES;
        #pragma unroll
        for (int ks = 0; ks < 4; ++ks) {
            uint32_t a[4][4], b[4][4];
            #pragma unroll
            for (int mt = 0; mt < 4; ++mt) {
                uint32_t off = (uint32_t)((a_row + mt * 16) * 128 + a_kb + ks * 32);
                ldsm_x4(a[mt][0], a[mt][1], a[mt][2], a[mt][3],
                        abase + STAGE_A + sw128(off));
            }
            #pragma unroll
            for (int ntp = 0; ntp < 4; ++ntp) {
                uint32_t off = (uint32_t)((b_row + ntp * 16) * 128 + b_kb + ks * 32);
                ldsm_x4(b[ntp][0], b[ntp][1], b[ntp][2], b[ntp][3],
                        abase + STAGE_B + sw128(off));
            }
            #pragma unroll
            for (int mt = 0; mt < 4; ++mt)
                #pragma unroll
                for (int nt = 0; nt < 8; ++nt) {
                    const int ntp = nt >> 1, hh = (nt & 1) * 2;
                    mma16816(c[mt][nt], a[mt], b[ntp][hh], b[ntp][hh + 1]);
                }
        }
    }

    // Epilogue: direct fp32 stores (each thread owns disjoint 2-wide slots)
    const int rbase = m0 + warp_m * 64 + (lane >> 2);
    const int cbase = n0 + warp_n * 64 + (lane & 3) * 2;
    #pragma unroll
    for (int mt = 0; mt < 4; ++mt) {
        #pragma unroll
        for (int nt = 0; nt < 8; ++nt) {
            float* p0 = out + (size_t)(rbase + mt * 16) * NDIM + cbase + nt * 8;
            float* p1 = p0 + 8 * NDIM;
            float2 v0 = make_float2(c[mt][nt][0], c[mt][nt][1]);
            float2 v1 = make_float2(c[mt][nt][2], c[mt][nt][3]);
            *reinterpret_cast<float2*>(p0) = v0;
            *reinterpret_cast<float2*>(p1) = v1;
        }
    }
}

// ---------------------------------------------------------------------------
// Launch
// ---------------------------------------------------------------------------
extern "C" void kernel_launch(void* const* d_in, const int* in_sizes, int n_in,
                              void* d_out, int out_size) {
    (void)in_sizes; (void)n_in; (void)out_size;
    const float* A = (const float*)d_in[0];   // [8192, 2048]
    const float* W = (const float*)d_in[1];   // [2048, 2048]
    float* out = (float*)d_out;               // [8192, 2048]

    convert_kernel<<<(int)(((size_t)MDIM * KDIM / 4) / 256), 256>>>(A);
    binarize_kernel<<<dim3(NDIM / 32, KDIM / 32), dim3(32, 8)>>>(W);

    static bool attr_set = false;
    if (!attr_set) {
        cudaFuncSetAttribute(gemm_kernel,
                             cudaFuncAttributeMaxDynamicSharedMemorySize, SMEM_TOTAL);
        attr_set = true;
    }
    gemm_kernel<<<(MDIM / BM) * (NDIM / BN), 128, SMEM_TOTAL>>>(out);
}